// round 1
// baseline (speedup 1.0000x reference)
#include <cuda_runtime.h>
#include <cuda_bf16.h>

// SSIM loss, fused single-pass: separable 11-tap Gaussian blur of
// {img1, img2, img1^2, img2^2, img1*img2} + elementwise SSIM + mean.
// Input: 2x [16,3,512,512] fp32. Output: 1 fp32 scalar (1 - mean(ssim_map)).

#define TILE_W 128
#define TILE_H 32
#define RAD    5
#define KW     11
#define SROWS  (TILE_H + 2 * RAD)   // 42
#define SCOLS  (TILE_W + 2 * RAD)   // 138
#define HH     512
#define WW     512
#define PLANES 48                   // 16*3
#define GX     (WW / TILE_W)        // 4
#define GY     (HH / TILE_H)        // 16
#define NBLK   (GX * GY * PLANES)   // 3072

__device__ float g_partials[NBLK];

__global__ void __launch_bounds__(TILE_W, 4)
ssim_main(const float* __restrict__ img1, const float* __restrict__ img2)
{
    __shared__ float s1[SROWS * SCOLS];
    __shared__ float s2[SROWS * SCOLS];

    const int t     = threadIdx.x;
    const int x0    = blockIdx.x * TILE_W;
    const int y0    = blockIdx.y * TILE_H;
    const int plane = blockIdx.z;
    const size_t base = (size_t)plane * (HH * WW);

    // Gaussian weights (sigma = 1.5), normalized. Cheap per-thread compute.
    float w[KW];
    {
        float s = 0.f;
        #pragma unroll
        for (int k = 0; k < KW; ++k) {
            float d = (float)(k - RAD);
            w[k] = expf(-d * d / (2.f * 1.5f * 1.5f));
            s += w[k];
        }
        float inv = 1.f / s;
        #pragma unroll
        for (int k = 0; k < KW; ++k) w[k] *= inv;
    }

    // Cooperative load of halo'd tile (zero padding outside image).
    const int total = SROWS * SCOLS;
    for (int idx = t; idx < total; idx += TILE_W) {
        int yy = idx / SCOLS;
        int xx = idx - yy * SCOLS;
        int gy = y0 + yy - RAD;
        int gx = x0 + xx - RAD;
        float v1 = 0.f, v2 = 0.f;
        if (gy >= 0 && gy < HH && gx >= 0 && gx < WW) {
            size_t off = base + (size_t)gy * WW + gx;
            v1 = img1[off];
            v2 = img2[off];
        }
        s1[idx] = v1;
        s2[idx] = v2;
    }
    __syncthreads();

    // Register ring of horizontal blurs for the 5 fields (11 rows deep).
    float rm1[KW], rm2[KW], rq1[KW], rq2[KW], rq12[KW];

    // Horizontal blur of the 5 fields at smem row yi, column t..t+10.
    auto hblur = [&](int yi, float& h1, float& h2, float& hq1, float& hq2, float& hq12) {
        const float* __restrict__ p1 = &s1[yi * SCOLS + t];
        const float* __restrict__ p2 = &s2[yi * SCOLS + t];
        float a1 = 0.f, a2 = 0.f, b1 = 0.f, b2 = 0.f, b12 = 0.f;
        #pragma unroll
        for (int k = 0; k < KW; ++k) {
            float va = p1[k];
            float vb = p2[k];
            float wa = w[k] * va;   // reused for q1 and q12
            float wb = w[k] * vb;
            a1  = fmaf(w[k], va, a1);
            a2  = fmaf(w[k], vb, a2);
            b1  = fmaf(wa, va, b1);
            b2  = fmaf(wb, vb, b2);
            b12 = fmaf(wa, vb, b12);
        }
        h1 = a1; h2 = a2; hq1 = b1; hq2 = b2; hq12 = b12;
    };

    // Prologue: fill ring slots 0..9 with input rows 0..9.
    #pragma unroll
    for (int j = 0; j < KW - 1; ++j)
        hblur(j, rm1[j], rm2[j], rq1[j], rq2[j], rq12[j]);

    const float C1 = 0.0001f;   // (0.01)^2
    const float C2 = 0.0009f;   // (0.03)^2
    float acc = 0.f;

    for (int oy = 0; oy < TILE_H; ++oy) {
        hblur(oy + KW - 1, rm1[KW - 1], rm2[KW - 1], rq1[KW - 1], rq2[KW - 1], rq12[KW - 1]);

        // Vertical blur over the ring.
        float m1 = 0.f, m2 = 0.f, q1 = 0.f, q2 = 0.f, q12 = 0.f;
        #pragma unroll
        for (int j = 0; j < KW; ++j) {
            m1  = fmaf(w[j], rm1[j],  m1);
            m2  = fmaf(w[j], rm2[j],  m2);
            q1  = fmaf(w[j], rq1[j],  q1);
            q2  = fmaf(w[j], rq2[j],  q2);
            q12 = fmaf(w[j], rq12[j], q12);
        }

        // SSIM map value.
        float mu12 = m1 * m2;
        float mu1s = m1 * m1;
        float mu2s = m2 * m2;
        float sa   = q1  - mu1s;
        float sb   = q2  - mu2s;
        float sab  = q12 - mu12;
        float num  = (2.f * mu12 + C1) * (2.f * sab + C2);
        float den  = (mu1s + mu2s + C1) * (sa + sb + C2);
        acc += __fdividef(num, den);

        // Shift ring.
        #pragma unroll
        for (int j = 0; j < KW - 1; ++j) {
            rm1[j]  = rm1[j + 1];
            rm2[j]  = rm2[j + 1];
            rq1[j]  = rq1[j + 1];
            rq2[j]  = rq2[j + 1];
            rq12[j] = rq12[j + 1];
        }
    }

    // Block reduction (deterministic; no atomics).
    #pragma unroll
    for (int o = 16; o; o >>= 1)
        acc += __shfl_xor_sync(0xFFFFFFFFu, acc, o);

    __shared__ float warpsum[TILE_W / 32];
    if ((t & 31) == 0) warpsum[t >> 5] = acc;
    __syncthreads();
    if (t == 0) {
        float bs = 0.f;
        #pragma unroll
        for (int i = 0; i < TILE_W / 32; ++i) bs += warpsum[i];
        g_partials[(blockIdx.z * GY + blockIdx.y) * GX + blockIdx.x] = bs;
    }
}

__global__ void ssim_reduce(float* __restrict__ out)
{
    __shared__ double sm[256];
    double a = 0.0;
    for (int i = threadIdx.x; i < NBLK; i += 256)
        a += (double)g_partials[i];
    sm[threadIdx.x] = a;
    __syncthreads();
    #pragma unroll
    for (int sft = 128; sft; sft >>= 1) {
        if (threadIdx.x < sft) sm[threadIdx.x] += sm[threadIdx.x + sft];
        __syncthreads();
    }
    if (threadIdx.x == 0) {
        double n = (double)PLANES * HH * WW;   // 12,582,912
        out[0] = (float)(1.0 - sm[0] / n);
    }
}

extern "C" void kernel_launch(void* const* d_in, const int* in_sizes, int n_in,
                              void* d_out, int out_size)
{
    (void)in_sizes; (void)n_in; (void)out_size;
    const float* img1 = (const float*)d_in[0];
    const float* img2 = (const float*)d_in[1];
    float* out = (float*)d_out;

    dim3 grid(GX, GY, PLANES);
    ssim_main<<<grid, TILE_W>>>(img1, img2);
    ssim_reduce<<<1, 256>>>(out);
}